// round 8
// baseline (speedup 1.0000x reference)
#include <cuda_runtime.h>
#include <cuda_fp16.h>
#include <math.h>
#include <stdint.h>

#define T_ 4096
#define I_ 2048
#define HD 2048
#define K_ 3
#define NCOL 18432            // 3*3H
#define CH 11264              // cols [0,CH) -> HMMA kernel; [CH,NCOL) -> FFMA kernel

// ---------------- scratch (device globals) ---------------------------------
__device__ float g_gi[(size_t)T_ * NCOL];        // raw GEMM out ~302MB
__device__ float g_Hall[(size_t)T_ * K_ * HD];   // ~100.7MB
__device__ __half g_xhi[(size_t)T_ * I_];
__device__ __half g_xlo[(size_t)T_ * I_];
__device__ __half g_whi[(size_t)CH * I_];
__device__ __half g_wlo[(size_t)CH * I_];
__device__ float g_D[(size_t)T_ * K_ * K_];
__device__ float g_selx[(size_t)T_ * K_];
__device__ unsigned int g_fw[T_];
__device__ int g_kk[T_];

// ---------------- helpers ---------------------------------------------------
__device__ __forceinline__ uint32_t smem_u32(const void* p) {
    uint32_t a;
    asm("{ .reg .u64 t; cvta.to.shared.u64 t, %1; cvt.u32.u64 %0, t; }" : "=r"(a) : "l"(p));
    return a;
}
__device__ __forceinline__ void cp16(uint32_t s, const void* g) {
    asm volatile("cp.async.cg.shared.global [%0], [%1], 16;" :: "r"(s), "l"(g));
}
#define CP_COMMIT() asm volatile("cp.async.commit_group;" ::: "memory")
#define CP_WAIT2()  asm volatile("cp.async.wait_group 2;" ::: "memory")

__device__ __forceinline__ void ldsm_x4(uint32_t& r0, uint32_t& r1, uint32_t& r2,
                                        uint32_t& r3, uint32_t a) {
    asm volatile("ldmatrix.sync.aligned.m8n8.x4.shared.b16 {%0,%1,%2,%3}, [%4];"
                 : "=r"(r0), "=r"(r1), "=r"(r2), "=r"(r3) : "r"(a));
}
__device__ __forceinline__ void mma16816(float* d, const uint32_t* a, uint32_t b0, uint32_t b1) {
    asm volatile("mma.sync.aligned.m16n8k16.row.col.f32.f16.f16.f32 "
                 "{%0,%1,%2,%3}, {%4,%5,%6,%7}, {%8,%9}, {%0,%1,%2,%3};"
                 : "+f"(d[0]), "+f"(d[1]), "+f"(d[2]), "+f"(d[3])
                 : "r"(a[0]), "r"(a[1]), "r"(a[2]), "r"(a[3]), "r"(b0), "r"(b1));
}

// ---------------------------------------------------------------------------
// K0: fp16 two-way split prep.
// ---------------------------------------------------------------------------
__global__ __launch_bounds__(256) void k0_split(
    const float* __restrict__ src, __half* __restrict__ hi,
    __half* __restrict__ lo, size_t n4)
{
    size_t i = (size_t)blockIdx.x * 256 + threadIdx.x;
    if (i >= n4) return;
    float4 v = *(const float4*)(src + i * 4);
    __half h[4], l[4];
    float vv[4] = {v.x, v.y, v.z, v.w};
#pragma unroll
    for (int q = 0; q < 4; q++) {
        h[q] = __float2half_rn(vv[q]);
        l[q] = __float2half_rn(vv[q] - __half2float(h[q]));
    }
    *(uint2*)(hi + i * 4) = *(uint2*)h;
    *(uint2*)(lo + i * 4) = *(uint2*)l;
}

// ---------------------------------------------------------------------------
// K1a: cols [0, CH) via mma.sync f16x3 split. CTA 128x128, 3-stage cp.async.
// ---------------------------------------------------------------------------
#define BK 32
#define ROWB 80
#define TILEB (128 * ROWB)
#define STAGEB (4 * TILEB)
#define NSTG 3
#define K1_SMEM (NSTG * STAGEB)   // 122880
#define NS (I_ / BK)              // 64

__global__ void __launch_bounds__(256, 1) k1_mma(
    const __half* __restrict__ xhi, const __half* __restrict__ xlo,
    const __half* __restrict__ whi, const __half* __restrict__ wlo)
{
    extern __shared__ char smem[];
    const uint32_t sbase = smem_u32(smem);
    const int tid = threadIdx.x;
    const int wid = tid >> 5;
    const int lane = tid & 31;

    const int t0 = blockIdx.x * 128;   // M
    const int c0 = blockIdx.y * 128;   // N < CH

    const int warpM = (wid & 3) * 32;
    const int warpN = (wid >> 2) * 64;

    float acc[2][8][4];
#pragma unroll
    for (int i = 0; i < 2; i++)
#pragma unroll
        for (int j = 0; j < 8; j++)
#pragma unroll
            for (int q = 0; q < 4; q++) acc[i][j][q] = 0.f;

    auto fetch = [&](int s) {
        const int stg = s % NSTG;
        const uint32_t bA_hi = sbase + stg * STAGEB;
        const uint32_t bA_lo = bA_hi + TILEB;
        const uint32_t bB_hi = bA_hi + 2 * TILEB;
        const uint32_t bB_lo = bA_hi + 3 * TILEB;
        const int k0 = s * BK;
#pragma unroll
        for (int it = 0; it < 2; it++) {
            int c = it * 256 + tid;
            int kc = c >> 7;
            int row = c & 127;
            uint32_t so = (uint32_t)(row * ROWB + kc * 16);
            size_t ga = (size_t)(t0 + row) * I_ + k0 + kc * 8;
            size_t gb = (size_t)(c0 + row) * I_ + k0 + kc * 8;
            cp16(bA_hi + so, xhi + ga);
            cp16(bA_lo + so, xlo + ga);
            cp16(bB_hi + so, whi + gb);
            cp16(bB_lo + so, wlo + gb);
        }
    };

    fetch(0); CP_COMMIT();
    fetch(1); CP_COMMIT();

    for (int s = 0; s < NS; s++) {
        if (s + 2 < NS) fetch(s + 2);
        CP_COMMIT();
        CP_WAIT2();
        __syncthreads();

        const int stg = s % NSTG;
        const uint32_t bA_hi = sbase + stg * STAGEB;
        const uint32_t bA_lo = bA_hi + TILEB;
        const uint32_t bB_hi = bA_hi + 2 * TILEB;
        const uint32_t bB_lo = bA_hi + 3 * TILEB;

#pragma unroll
        for (int kc = 0; kc < 2; kc++) {
            const uint32_t kb = kc * 32 + (lane >> 4) * 16;
            const uint32_t rsel = (lane & 15);

            uint32_t Ah[2][4], Al[2][4];
#pragma unroll
            for (int i = 0; i < 2; i++) {
                uint32_t off = (uint32_t)((warpM + i * 16 + rsel) * ROWB) + kb;
                ldsm_x4(Ah[i][0], Ah[i][1], Ah[i][2], Ah[i][3], bA_hi + off);
                ldsm_x4(Al[i][0], Al[i][1], Al[i][2], Al[i][3], bA_lo + off);
            }
            uint32_t Bh[4][4], Bl[4][4];
#pragma unroll
            for (int g = 0; g < 4; g++) {
                uint32_t off = (uint32_t)((warpN + g * 16 + rsel) * ROWB) + kb;
                ldsm_x4(Bh[g][0], Bh[g][1], Bh[g][2], Bh[g][3], bB_hi + off);
                ldsm_x4(Bl[g][0], Bl[g][1], Bl[g][2], Bl[g][3], bB_lo + off);
            }
#pragma unroll
            for (int i = 0; i < 2; i++) {
#pragma unroll
                for (int j = 0; j < 8; j++) {
                    int g = j >> 1, sel = j & 1;
                    uint32_t bh0 = Bh[g][sel], bh1 = Bh[g][sel + 2];
                    uint32_t bl0 = Bl[g][sel], bl1 = Bl[g][sel + 2];
                    mma16816(acc[i][j], Ah[i], bh0, bh1);
                    mma16816(acc[i][j], Ah[i], bl0, bl1);
                    mma16816(acc[i][j], Al[i], bh0, bh1);
                }
            }
        }
        __syncthreads();
    }

#pragma unroll
    for (int i = 0; i < 2; i++) {
#pragma unroll
        for (int j = 0; j < 8; j++) {
            int row = t0 + warpM + i * 16 + (lane >> 2);
            int col = c0 + warpN + j * 8 + (lane & 3) * 2;
            float2 u0 = make_float2(acc[i][j][0], acc[i][j][1]);
            float2 u1 = make_float2(acc[i][j][2], acc[i][j][3]);
            *(float2*)&g_gi[(size_t)row * NCOL + col] = u0;
            *(float2*)&g_gi[(size_t)(row + 8) * NCOL + col] = u1;
        }
    }
}

// ---------------------------------------------------------------------------
// K1b: cols [CH, NCOL) via fp32 SIMT FFMA (idle pipe during k1_mma).
// Tile M=128, N=64, KT=16; micro 8x4. Reg-capped for co-residency.
// ---------------------------------------------------------------------------
#define F_BM 128
#define F_BN 64
#define F_KT 16

__global__ __launch_bounds__(256, 3) void k1_ffma(
    const float* __restrict__ xs, const float* __restrict__ Wih)
{
    __shared__ float As[F_KT][F_BM + 4];
    __shared__ float Bs[F_KT][F_BN + 4];

    const int t0 = blockIdx.x * F_BM;          // M tile (fast -> B strip reuse)
    const int c0 = CH + blockIdx.y * F_BN;     // col tile in FFMA range
    const int tid = threadIdx.x;
    const int tx = tid & 15;
    const int ty = tid >> 4;

    float acc[8][4];
#pragma unroll
    for (int m = 0; m < 8; m++)
#pragma unroll
        for (int n = 0; n < 4; n++) acc[m][n] = 0.f;

    // A: 512 float4 -> 2/thread;  B: 256 float4 -> 1/thread
    const int ar0 = tid >> 2, ak0 = (tid & 3) * 4;
    const int ar1 = (tid + 256) >> 2, ak1 = ak0;   // (tid+256)&3 == tid&3
    const int br = tid >> 2, bk = (tid & 3) * 4;

    const float* Ap0 = xs + (size_t)(t0 + ar0) * I_ + ak0;
    const float* Ap1 = xs + (size_t)(t0 + ar1) * I_ + ak1;
    const float* Bp  = Wih + (size_t)(c0 + br) * I_ + bk;

    float4 a0 = *(const float4*)(Ap0);
    float4 a1 = *(const float4*)(Ap1);
    float4 b0 = *(const float4*)(Bp);

    for (int k0 = 0; k0 < I_; k0 += F_KT) {
        __syncthreads();
        As[ak0 + 0][ar0] = a0.x; As[ak0 + 1][ar0] = a0.y;
        As[ak0 + 2][ar0] = a0.z; As[ak0 + 3][ar0] = a0.w;
        As[ak1 + 0][ar1] = a1.x; As[ak1 + 1][ar1] = a1.y;
        As[ak1 + 2][ar1] = a1.z; As[ak1 + 3][ar1] = a1.w;
        Bs[bk + 0][br] = b0.x; Bs[bk + 1][br] = b0.y;
        Bs[bk + 2][br] = b0.z; Bs[bk + 3][br] = b0.w;
        __syncthreads();

        int kn = k0 + F_KT;
        if (kn < I_) {
            a0 = *(const float4*)(Ap0 + kn);
            a1 = *(const float4*)(Ap1 + kn);
            b0 = *(const float4*)(Bp + kn);
        }

#pragma unroll
        for (int kk = 0; kk < F_KT; kk++) {
            float4 amv0 = *(const float4*)&As[kk][ty * 8];
            float4 amv1 = *(const float4*)&As[kk][ty * 8 + 4];
            float4 bnv  = *(const float4*)&Bs[kk][tx * 4];
            float am[8] = {amv0.x, amv0.y, amv0.z, amv0.w,
                           amv1.x, amv1.y, amv1.z, amv1.w};
            float bn[4] = {bnv.x, bnv.y, bnv.z, bnv.w};
#pragma unroll
            for (int m = 0; m < 8; m++)
#pragma unroll
                for (int n = 0; n < 4; n++)
                    acc[m][n] = fmaf(am[m], bn[n], acc[m][n]);
        }
    }

#pragma unroll
    for (int m = 0; m < 8; m++) {
        int row = t0 + ty * 8 + m;
        float4 o = make_float4(acc[m][0], acc[m][1], acc[m][2], acc[m][3]);
        *(float4*)&g_gi[(size_t)row * NCOL + c0 + tx * 4] = o;
    }
}

// ---------------------------------------------------------------------------
// K1c: elementwise gates  Hall[t][k][o]
// ---------------------------------------------------------------------------
__global__ __launch_bounds__(256) void k_gates(
    const float* __restrict__ bih, const float* __restrict__ bhh)
{
    size_t idx = (size_t)blockIdx.x * 256 + threadIdx.x;
    int o4 = (int)(idx % (HD / 4));
    int k  = (int)((idx / (HD / 4)) % K_);
    int t  = (int)(idx / ((size_t)K_ * (HD / 4)));

    const float* base = g_gi + (size_t)t * NCOL + (size_t)k * 3 * HD + o4 * 4;
    float4 ir4 = *(const float4*)(base);
    float4 iz4 = *(const float4*)(base + HD);
    float4 in4 = *(const float4*)(base + 2 * HD);

    const float* bi = bih + (size_t)k * 3 * HD;
    const float* bh = bhh + (size_t)k * 3 * HD;
    float4 br = *(const float4*)(bi + o4 * 4);
    float4 bz = *(const float4*)(bi + HD + o4 * 4);
    float4 bn = *(const float4*)(bi + 2 * HD + o4 * 4);
    float4 hr = *(const float4*)(bh + o4 * 4);
    float4 hz = *(const float4*)(bh + HD + o4 * 4);
    float4 hn = *(const float4*)(bh + 2 * HD + o4 * 4);

    float irs[4] = {ir4.x, ir4.y, ir4.z, ir4.w};
    float izs[4] = {iz4.x, iz4.y, iz4.z, iz4.w};
    float ins[4] = {in4.x, in4.y, in4.z, in4.w};
    float brs[4] = {br.x, br.y, br.z, br.w};
    float bzs[4] = {bz.x, bz.y, bz.z, bz.w};
    float bns[4] = {bn.x, bn.y, bn.z, bn.w};
    float hrs[4] = {hr.x, hr.y, hr.z, hr.w};
    float hzs[4] = {hz.x, hz.y, hz.z, hz.w};
    float hns[4] = {hn.x, hn.y, hn.z, hn.w};

    float res[4];
#pragma unroll
    for (int n = 0; n < 4; n++) {
        float r = 1.0f / (1.0f + expf(-(irs[n] + brs[n] + hrs[n])));
        float z = 1.0f / (1.0f + expf(-(izs[n] + bzs[n] + hzs[n])));
        float nn = tanhf(ins[n] + bns[n] + r * hns[n]);
        res[n] = (1.0f - z) * nn;
    }
    float4 o;
    o.x = res[0]; o.y = res[1]; o.z = res[2]; o.w = res[3];
    *(float4*)&g_Hall[((size_t)t * K_ + k) * HD + o4 * 4] = o;
}

// ---------------------------------------------------------------------------
// K2: D + sel_x
// ---------------------------------------------------------------------------
__global__ __launch_bounds__(256) void k2_Dselx(
    const float* __restrict__ xs, const float* __restrict__ Wsel,
    const float* __restrict__ bsel)
{
    const int t = blockIdx.x;
    float aD[9] = {0.f, 0.f, 0.f, 0.f, 0.f, 0.f, 0.f, 0.f, 0.f};
    float aS[3] = {0.f, 0.f, 0.f};

    const float* hrow = g_Hall + (size_t)t * K_ * HD;
    const float* xrow = xs + (size_t)t * I_;
    const int WS = HD + I_;

    for (int h = threadIdx.x; h < HD; h += 256) {
        float w0 = Wsel[0 * WS + h];
        float w1 = Wsel[1 * WS + h];
        float w2 = Wsel[2 * WS + h];
#pragma unroll
        for (int j = 0; j < 3; j++) {
            float hv = hrow[(size_t)j * HD + h];
            aD[j * 3 + 0] = fmaf(hv, w0, aD[j * 3 + 0]);
            aD[j * 3 + 1] = fmaf(hv, w1, aD[j * 3 + 1]);
            aD[j * 3 + 2] = fmaf(hv, w2, aD[j * 3 + 2]);
        }
    }
    for (int i = threadIdx.x; i < I_; i += 256) {
        float xv = xrow[i];
        aS[0] = fmaf(xv, Wsel[0 * WS + HD + i], aS[0]);
        aS[1] = fmaf(xv, Wsel[1 * WS + HD + i], aS[1]);
        aS[2] = fmaf(xv, Wsel[2 * WS + HD + i], aS[2]);
    }

    float vals[12];
#pragma unroll
    for (int v = 0; v < 9; v++) vals[v] = aD[v];
#pragma unroll
    for (int v = 0; v < 3; v++) vals[9 + v] = aS[v];

    __shared__ float red[12][8];
    int lane = threadIdx.x & 31, w = threadIdx.x >> 5;
#pragma unroll
    for (int v = 0; v < 12; v++) {
        float s = vals[v];
        for (int off = 16; off > 0; off >>= 1)
            s += __shfl_down_sync(0xffffffffu, s, off);
        if (lane == 0) red[v][w] = s;
    }
    __syncthreads();
    if (threadIdx.x < 12) {
        float s = 0.f;
#pragma unroll
        for (int ww = 0; ww < 8; ww++) s += red[threadIdx.x][ww];
        if (threadIdx.x < 9)
            g_D[(size_t)t * 9 + threadIdx.x] = s;
        else
            g_selx[(size_t)t * 3 + (threadIdx.x - 9)] = s + bsel[threadIdx.x - 9];
    }
}

// ---------------------------------------------------------------------------
// K3: packed transition maps
// ---------------------------------------------------------------------------
__global__ void k3_f()
{
    int t = blockIdx.x * blockDim.x + threadIdx.x;
    if (t < 1 || t >= T_) return;
    const float* d = g_D + (size_t)(t - 1) * 9;
    float s0 = g_selx[t * 3 + 0];
    float s1 = g_selx[t * 3 + 1];
    float s2 = g_selx[t * 3 + 2];
    unsigned int word = 0;
#pragma unroll
    for (int j = 0; j < 3; j++) {
        float l0 = d[j * 3 + 0] + s0;
        float l1 = d[j * 3 + 1] + s1;
        float l2 = d[j * 3 + 2] + s2;
        int best = 0; float bv = l0;
        if (l1 > bv) { bv = l1; best = 1; }
        if (l2 > bv) { best = 2; }
        word |= (unsigned int)best << (8 * j);
    }
    g_fw[t] = word;
}

// ---------------------------------------------------------------------------
// K4: sequential 3-state automaton composition
// ---------------------------------------------------------------------------
__global__ __launch_bounds__(256) void k4_scan()
{
    __shared__ unsigned int sw[T_];
    for (int i = threadIdx.x; i < T_; i += 256) sw[i] = g_fw[i];
    __syncthreads();
    if (threadIdx.x == 0) {
        int cur = 0;
        g_kk[0] = 0;
        for (int t = 1; t < T_; t++) {
            unsigned int w = sw[t];
            cur = (int)((w >> (cur << 3)) & 0xffu);
            g_kk[t] = cur;
        }
    }
}

// ---------------------------------------------------------------------------
// K5: gather
// ---------------------------------------------------------------------------
__global__ __launch_bounds__(256) void k5_gather(float* __restrict__ out)
{
    int t = blockIdx.x;
    int tt = (t == T_) ? (T_ - 1) : t;
    int sel = g_kk[tt];
    const float4* src = (const float4*)(g_Hall + ((size_t)tt * K_ + sel) * HD);
    float4* dst = (float4*)(out + (size_t)t * HD);
    for (int i = threadIdx.x; i < HD / 4; i += 256) dst[i] = src[i];
}

// ---------------------------------------------------------------------------
extern "C" void kernel_launch(void* const* d_in, const int* in_sizes, int n_in,
                              void* d_out, int out_size)
{
    const float* x    = (const float*)d_in[0];
    const float* Wih  = (const float*)d_in[1];
    // d_in[2] = W_hh : unused (only b_hh enters the math)
    const float* bih  = (const float*)d_in[3];
    const float* bhh  = (const float*)d_in[4];
    const float* Wsel = (const float*)d_in[5];
    const float* bsel = (const float*)d_in[6];
    float* out = (float*)d_out;

    __half *xhi, *xlo, *whi, *wlo;
    cudaGetSymbolAddress((void**)&xhi, g_xhi);
    cudaGetSymbolAddress((void**)&xlo, g_xlo);
    cudaGetSymbolAddress((void**)&whi, g_whi);
    cudaGetSymbolAddress((void**)&wlo, g_wlo);

    cudaFuncSetAttribute(k1_mma, cudaFuncAttributeMaxDynamicSharedMemorySize, K1_SMEM);

    // Fork a second stream inside the capture: FFMA branch runs concurrently
    // with the split-prep + HMMA branch (different execution pipes).
    cudaStream_t s2 = 0;
    cudaEvent_t eF = 0, eJ = 0;
    bool forked = (cudaStreamCreateWithFlags(&s2, cudaStreamNonBlocking) == cudaSuccess)
               && (cudaEventCreateWithFlags(&eF, cudaEventDisableTiming) == cudaSuccess)
               && (cudaEventCreateWithFlags(&eJ, cudaEventDisableTiming) == cudaSuccess);
    cudaStream_t sF = forked ? s2 : (cudaStream_t)0;

    if (forked) {
        cudaEventRecord(eF, 0);
        cudaStreamWaitEvent(sF, eF, 0);
    }
    // FFMA branch: cols [CH, NCOL), reads fp32 inputs directly (no prep dep)
    {
        dim3 gF(T_ / F_BM, (NCOL - CH) / F_BN);   // (32, 112), M-fast
        k1_ffma<<<gF, 256, 0, sF>>>(x, Wih);
    }

    // HMMA branch on stream 0: prep + mma over cols [0, CH)
    size_t nx4 = (size_t)T_ * I_ / 4;
    size_t nw4 = (size_t)CH * I_ / 4;
    k0_split<<<(int)((nx4 + 255) / 256), 256>>>(x, xhi, xlo, nx4);
    k0_split<<<(int)((nw4 + 255) / 256), 256>>>(Wih, whi, wlo, nw4);

    dim3 g1(T_ / 128, CH / 128);   // (32, 88), M-fast
    k1_mma<<<g1, 256, K1_SMEM>>>(xhi, xlo, whi, wlo);

    if (forked) {
        cudaEventRecord(eJ, sF);
        cudaStreamWaitEvent(0, eJ, 0);
    }

    k_gates<<<(int)(((size_t)T_ * K_ * (HD / 4)) / 256), 256>>>(bih, bhh);
    k2_Dselx<<<T_, 256>>>(x, Wsel, bsel);
    k3_f<<<(T_ + 255) / 256, 256>>>();
    k4_scan<<<1, 256>>>();
    k5_gather<<<T_ + 1, 256>>>(out);
    // Note: stream/events intentionally not destroyed here — they may still be
    // referenced by the capture in progress; kernel_launch is invoked only a
    // handful of times so the leak is bounded and allocation-guard-safe.
}

// round 9
// speedup vs baseline: 1.2954x; 1.2954x over previous
#include <cuda_runtime.h>
#include <cuda_fp16.h>
#include <math.h>
#include <stdint.h>

#define T_ 4096
#define I_ 2048
#define HD 2048
#define K_ 3
#define NCOL 18432            // 3*3H

// ---------------- scratch (device globals) ---------------------------------
__device__ float g_gi[(size_t)T_ * NCOL];        // raw GEMM out ~302MB
__device__ float g_Hall[(size_t)T_ * K_ * HD];   // ~100.7MB
__device__ __half g_xhi[(size_t)T_ * I_];
__device__ __half g_xlo[(size_t)T_ * I_];
__device__ __half g_whi[(size_t)NCOL * I_];
__device__ __half g_wlo[(size_t)NCOL * I_];
__device__ float g_D[(size_t)T_ * K_ * K_];
__device__ float g_selx[(size_t)T_ * K_];
__device__ unsigned int g_fw[T_];
__device__ int g_kk[T_];

// ---------------- helpers ---------------------------------------------------
__device__ __forceinline__ uint32_t smem_u32(const void* p) {
    uint32_t a;
    asm("{ .reg .u64 t; cvta.to.shared.u64 t, %1; cvt.u32.u64 %0, t; }" : "=r"(a) : "l"(p));
    return a;
}
__device__ __forceinline__ void cp16(uint32_t s, const void* g) {
    asm volatile("cp.async.cg.shared.global [%0], [%1], 16;" :: "r"(s), "l"(g));
}
#define CP_COMMIT() asm volatile("cp.async.commit_group;" ::: "memory")
#define CP_WAIT0()  asm volatile("cp.async.wait_group 0;" ::: "memory")

__device__ __forceinline__ void ldsm_x4(uint32_t& r0, uint32_t& r1, uint32_t& r2,
                                        uint32_t& r3, uint32_t a) {
    asm volatile("ldmatrix.sync.aligned.m8n8.x4.shared.b16 {%0,%1,%2,%3}, [%4];"
                 : "=r"(r0), "=r"(r1), "=r"(r2), "=r"(r3) : "r"(a));
}
__device__ __forceinline__ void mma16816(float* d, const uint32_t* a, uint32_t b0, uint32_t b1) {
    asm volatile("mma.sync.aligned.m16n8k16.row.col.f32.f16.f16.f32 "
                 "{%0,%1,%2,%3}, {%4,%5,%6,%7}, {%8,%9}, {%0,%1,%2,%3};"
                 : "+f"(d[0]), "+f"(d[1]), "+f"(d[2]), "+f"(d[3])
                 : "r"(a[0]), "r"(a[1]), "r"(a[2]), "r"(a[3]), "r"(b0), "r"(b1));
}

// ---------------------------------------------------------------------------
// K0: fp16 two-way split prep.
// ---------------------------------------------------------------------------
__global__ __launch_bounds__(256) void k0_split(
    const float* __restrict__ src, __half* __restrict__ hi,
    __half* __restrict__ lo, size_t n4)
{
    size_t i = (size_t)blockIdx.x * 256 + threadIdx.x;
    if (i >= n4) return;
    float4 v = *(const float4*)(src + i * 4);
    __half h[4], l[4];
    float vv[4] = {v.x, v.y, v.z, v.w};
#pragma unroll
    for (int q = 0; q < 4; q++) {
        h[q] = __float2half_rn(vv[q]);
        l[q] = __float2half_rn(vv[q] - __half2float(h[q]));
    }
    *(uint2*)(hi + i * 4) = *(uint2*)h;
    *(uint2*)(lo + i * 4) = *(uint2*)l;
}

// ---------------------------------------------------------------------------
// K1: C[4096,18432] = x @ Wih^T via mma.sync f16x3 split (22-bit effective).
// CTA 128x128, double-buffered cp.async (2 stages, 80KB smem -> 2 CTAs/SM),
// ONE __syncthreads per stage:
//   wait_group 0 (stage s landed) -> sync (also proves compute(s-1) done in
//   all warps) -> fetch(s+1) overwrites the other buffer async -> compute(s).
// ---------------------------------------------------------------------------
#define BK 32
#define ROWB 80
#define TILEB (128 * ROWB)        // 10240
#define STAGEB (4 * TILEB)        // 40960
#define NSTG 2
#define K1_SMEM (NSTG * STAGEB)   // 81920 -> two CTAs per SM
#define NS (I_ / BK)              // 64

__global__ void __launch_bounds__(256, 2) k1_mma(
    const __half* __restrict__ xhi, const __half* __restrict__ xlo,
    const __half* __restrict__ whi, const __half* __restrict__ wlo)
{
    extern __shared__ char smem[];
    const uint32_t sbase = smem_u32(smem);
    const int tid = threadIdx.x;
    const int wid = tid >> 5;
    const int lane = tid & 31;

    const int t0 = blockIdx.x * 128;   // M
    const int c0 = blockIdx.y * 128;   // N

    const int warpM = (wid & 3) * 32;
    const int warpN = (wid >> 2) * 64;

    float acc[2][8][4];
#pragma unroll
    for (int i = 0; i < 2; i++)
#pragma unroll
        for (int j = 0; j < 8; j++)
#pragma unroll
            for (int q = 0; q < 4; q++) acc[i][j][q] = 0.f;

    auto fetch = [&](int s) {
        const int stg = s & 1;
        const uint32_t bA_hi = sbase + stg * STAGEB;
        const uint32_t bA_lo = bA_hi + TILEB;
        const uint32_t bB_hi = bA_hi + 2 * TILEB;
        const uint32_t bB_lo = bA_hi + 3 * TILEB;
        const int k0 = s * BK;
#pragma unroll
        for (int it = 0; it < 2; it++) {
            int c = it * 256 + tid;
            int kc = c >> 7;
            int row = c & 127;
            uint32_t so = (uint32_t)(row * ROWB + kc * 16);
            size_t ga = (size_t)(t0 + row) * I_ + k0 + kc * 8;
            size_t gb = (size_t)(c0 + row) * I_ + k0 + kc * 8;
            cp16(bA_hi + so, xhi + ga);
            cp16(bA_lo + so, xlo + ga);
            cp16(bB_hi + so, whi + gb);
            cp16(bB_lo + so, wlo + gb);
        }
    };

    fetch(0); CP_COMMIT();

    for (int s = 0; s < NS; s++) {
        CP_WAIT0();          // stage s data landed
        __syncthreads();     // publish; all warps done with buffer (s+1)&1

        if (s + 1 < NS) { fetch(s + 1); CP_COMMIT(); }  // async during compute

        const int stg = s & 1;
        const uint32_t bA_hi = sbase + stg * STAGEB;
        const uint32_t bA_lo = bA_hi + TILEB;
        const uint32_t bB_hi = bA_hi + 2 * TILEB;
        const uint32_t bB_lo = bA_hi + 3 * TILEB;

#pragma unroll
        for (int kc = 0; kc < 2; kc++) {
            const uint32_t kb = kc * 32 + (lane >> 4) * 16;
            const uint32_t rsel = (lane & 15);

            uint32_t Ah[2][4], Al[2][4];
#pragma unroll
            for (int i = 0; i < 2; i++) {
                uint32_t off = (uint32_t)((warpM + i * 16 + rsel) * ROWB) + kb;
                ldsm_x4(Ah[i][0], Ah[i][1], Ah[i][2], Ah[i][3], bA_hi + off);
                ldsm_x4(Al[i][0], Al[i][1], Al[i][2], Al[i][3], bA_lo + off);
            }
            uint32_t Bh[4][4], Bl[4][4];
#pragma unroll
            for (int g = 0; g < 4; g++) {
                uint32_t off = (uint32_t)((warpN + g * 16 + rsel) * ROWB) + kb;
                ldsm_x4(Bh[g][0], Bh[g][1], Bh[g][2], Bh[g][3], bB_hi + off);
                ldsm_x4(Bl[g][0], Bl[g][1], Bl[g][2], Bl[g][3], bB_lo + off);
            }
#pragma unroll
            for (int i = 0; i < 2; i++) {
#pragma unroll
                for (int j = 0; j < 8; j++) {
                    int g = j >> 1, sel = j & 1;
                    uint32_t bh0 = Bh[g][sel], bh1 = Bh[g][sel + 2];
                    uint32_t bl0 = Bl[g][sel], bl1 = Bl[g][sel + 2];
                    mma16816(acc[i][j], Ah[i], bh0, bh1);   // hi*hi
                    mma16816(acc[i][j], Ah[i], bl0, bl1);   // hi*lo
                    mma16816(acc[i][j], Al[i], bh0, bh1);   // lo*hi
                }
            }
        }
    }

    // epilogue: acc -> g_gi
#pragma unroll
    for (int i = 0; i < 2; i++) {
#pragma unroll
        for (int j = 0; j < 8; j++) {
            int row = t0 + warpM + i * 16 + (lane >> 2);
            int col = c0 + warpN + j * 8 + (lane & 3) * 2;
            float2 u0 = make_float2(acc[i][j][0], acc[i][j][1]);
            float2 u1 = make_float2(acc[i][j][2], acc[i][j][3]);
            *(float2*)&g_gi[(size_t)row * NCOL + col] = u0;
            *(float2*)&g_gi[(size_t)(row + 8) * NCOL + col] = u1;
        }
    }
}

// ---------------------------------------------------------------------------
// K1b: elementwise gates  Hall[t][k][o]
// ---------------------------------------------------------------------------
__global__ __launch_bounds__(256) void k_gates(
    const float* __restrict__ bih, const float* __restrict__ bhh)
{
    size_t idx = (size_t)blockIdx.x * 256 + threadIdx.x;
    int o4 = (int)(idx % (HD / 4));
    int k  = (int)((idx / (HD / 4)) % K_);
    int t  = (int)(idx / ((size_t)K_ * (HD / 4)));

    const float* base = g_gi + (size_t)t * NCOL + (size_t)k * 3 * HD + o4 * 4;
    float4 ir4 = *(const float4*)(base);
    float4 iz4 = *(const float4*)(base + HD);
    float4 in4 = *(const float4*)(base + 2 * HD);

    const float* bi = bih + (size_t)k * 3 * HD;
    const float* bh = bhh + (size_t)k * 3 * HD;
    float4 br = *(const float4*)(bi + o4 * 4);
    float4 bz = *(const float4*)(bi + HD + o4 * 4);
    float4 bn = *(const float4*)(bi + 2 * HD + o4 * 4);
    float4 hr = *(const float4*)(bh + o4 * 4);
    float4 hz = *(const float4*)(bh + HD + o4 * 4);
    float4 hn = *(const float4*)(bh + 2 * HD + o4 * 4);

    float irs[4] = {ir4.x, ir4.y, ir4.z, ir4.w};
    float izs[4] = {iz4.x, iz4.y, iz4.z, iz4.w};
    float ins[4] = {in4.x, in4.y, in4.z, in4.w};
    float brs[4] = {br.x, br.y, br.z, br.w};
    float bzs[4] = {bz.x, bz.y, bz.z, bz.w};
    float bns[4] = {bn.x, bn.y, bn.z, bn.w};
    float hrs[4] = {hr.x, hr.y, hr.z, hr.w};
    float hzs[4] = {hz.x, hz.y, hz.z, hz.w};
    float hns[4] = {hn.x, hn.y, hn.z, hn.w};

    float res[4];
#pragma unroll
    for (int n = 0; n < 4; n++) {
        float r = 1.0f / (1.0f + expf(-(irs[n] + brs[n] + hrs[n])));
        float z = 1.0f / (1.0f + expf(-(izs[n] + bzs[n] + hzs[n])));
        float nn = tanhf(ins[n] + bns[n] + r * hns[n]);
        res[n] = (1.0f - z) * nn;
    }
    float4 o;
    o.x = res[0]; o.y = res[1]; o.z = res[2]; o.w = res[3];
    *(float4*)&g_Hall[((size_t)t * K_ + k) * HD + o4 * 4] = o;
}

// ---------------------------------------------------------------------------
// K2: D + sel_x
// ---------------------------------------------------------------------------
__global__ __launch_bounds__(256) void k2_Dselx(
    const float* __restrict__ xs, const float* __restrict__ Wsel,
    const float* __restrict__ bsel)
{
    const int t = blockIdx.x;
    float aD[9] = {0.f, 0.f, 0.f, 0.f, 0.f, 0.f, 0.f, 0.f, 0.f};
    float aS[3] = {0.f, 0.f, 0.f};

    const float* hrow = g_Hall + (size_t)t * K_ * HD;
    const float* xrow = xs + (size_t)t * I_;
    const int WS = HD + I_;

    for (int h = threadIdx.x; h < HD; h += 256) {
        float w0 = Wsel[0 * WS + h];
        float w1 = Wsel[1 * WS + h];
        float w2 = Wsel[2 * WS + h];
#pragma unroll
        for (int j = 0; j < 3; j++) {
            float hv = hrow[(size_t)j * HD + h];
            aD[j * 3 + 0] = fmaf(hv, w0, aD[j * 3 + 0]);
            aD[j * 3 + 1] = fmaf(hv, w1, aD[j * 3 + 1]);
            aD[j * 3 + 2] = fmaf(hv, w2, aD[j * 3 + 2]);
        }
    }
    for (int i = threadIdx.x; i < I_; i += 256) {
        float xv = xrow[i];
        aS[0] = fmaf(xv, Wsel[0 * WS + HD + i], aS[0]);
        aS[1] = fmaf(xv, Wsel[1 * WS + HD + i], aS[1]);
        aS[2] = fmaf(xv, Wsel[2 * WS + HD + i], aS[2]);
    }

    float vals[12];
#pragma unroll
    for (int v = 0; v < 9; v++) vals[v] = aD[v];
#pragma unroll
    for (int v = 0; v < 3; v++) vals[9 + v] = aS[v];

    __shared__ float red[12][8];
    int lane = threadIdx.x & 31, w = threadIdx.x >> 5;
#pragma unroll
    for (int v = 0; v < 12; v++) {
        float s = vals[v];
        for (int off = 16; off > 0; off >>= 1)
            s += __shfl_down_sync(0xffffffffu, s, off);
        if (lane == 0) red[v][w] = s;
    }
    __syncthreads();
    if (threadIdx.x < 12) {
        float s = 0.f;
#pragma unroll
        for (int ww = 0; ww < 8; ww++) s += red[threadIdx.x][ww];
        if (threadIdx.x < 9)
            g_D[(size_t)t * 9 + threadIdx.x] = s;
        else
            g_selx[(size_t)t * 3 + (threadIdx.x - 9)] = s + bsel[threadIdx.x - 9];
    }
}

// ---------------------------------------------------------------------------
// K3: packed transition maps
// ---------------------------------------------------------------------------
__global__ void k3_f()
{
    int t = blockIdx.x * blockDim.x + threadIdx.x;
    if (t < 1 || t >= T_) return;
    const float* d = g_D + (size_t)(t - 1) * 9;
    float s0 = g_selx[t * 3 + 0];
    float s1 = g_selx[t * 3 + 1];
    float s2 = g_selx[t * 3 + 2];
    unsigned int word = 0;
#pragma unroll
    for (int j = 0; j < 3; j++) {
        float l0 = d[j * 3 + 0] + s0;
        float l1 = d[j * 3 + 1] + s1;
        float l2 = d[j * 3 + 2] + s2;
        int best = 0; float bv = l0;
        if (l1 > bv) { bv = l1; best = 1; }
        if (l2 > bv) { best = 2; }
        word |= (unsigned int)best << (8 * j);
    }
    g_fw[t] = word;
}

// ---------------------------------------------------------------------------
// K4: sequential 3-state automaton composition
// ---------------------------------------------------------------------------
__global__ __launch_bounds__(256) void k4_scan()
{
    __shared__ unsigned int sw[T_];
    for (int i = threadIdx.x; i < T_; i += 256) sw[i] = g_fw[i];
    __syncthreads();
    if (threadIdx.x == 0) {
        int cur = 0;
        g_kk[0] = 0;
        for (int t = 1; t < T_; t++) {
            unsigned int w = sw[t];
            cur = (int)((w >> (cur << 3)) & 0xffu);
            g_kk[t] = cur;
        }
    }
}

// ---------------------------------------------------------------------------
// K5: gather
// ---------------------------------------------------------------------------
__global__ __launch_bounds__(256) void k5_gather(float* __restrict__ out)
{
    int t = blockIdx.x;
    int tt = (t == T_) ? (T_ - 1) : t;
    int sel = g_kk[tt];
    const float4* src = (const float4*)(g_Hall + ((size_t)tt * K_ + sel) * HD);
    float4* dst = (float4*)(out + (size_t)t * HD);
    for (int i = threadIdx.x; i < HD / 4; i += 256) dst[i] = src[i];
}

// ---------------------------------------------------------------------------
extern "C" void kernel_launch(void* const* d_in, const int* in_sizes, int n_in,
                              void* d_out, int out_size)
{
    const float* x    = (const float*)d_in[0];
    const float* Wih  = (const float*)d_in[1];
    // d_in[2] = W_hh : unused (only b_hh enters the math)
    const float* bih  = (const float*)d_in[3];
    const float* bhh  = (const float*)d_in[4];
    const float* Wsel = (const float*)d_in[5];
    const float* bsel = (const float*)d_in[6];
    float* out = (float*)d_out;

    __half *xhi, *xlo, *whi, *wlo;
    cudaGetSymbolAddress((void**)&xhi, g_xhi);
    cudaGetSymbolAddress((void**)&xlo, g_xlo);
    cudaGetSymbolAddress((void**)&whi, g_whi);
    cudaGetSymbolAddress((void**)&wlo, g_wlo);

    cudaFuncSetAttribute(k1_mma, cudaFuncAttributeMaxDynamicSharedMemorySize, K1_SMEM);

    size_t nx4 = (size_t)T_ * I_ / 4;
    size_t nw4 = (size_t)NCOL * I_ / 4;
    k0_split<<<(int)((nx4 + 255) / 256), 256>>>(x, xhi, xlo, nx4);
    k0_split<<<(int)((nw4 + 255) / 256), 256>>>(Wih, whi, wlo, nw4);

    dim3 g1(T_ / 128, NCOL / 128);  // (32, 144), M-fast -> A stays L2-resident
    k1_mma<<<g1, 256, K1_SMEM>>>(xhi, xlo, whi, wlo);

    k_gates<<<(int)(((size_t)T_ * K_ * (HD / 4)) / 256), 256>>>(bih, bhh);
    k2_Dselx<<<T_, 256>>>(x, Wsel, bsel);
    k3_f<<<(T_ + 255) / 256, 256>>>();
    k4_scan<<<1, 256>>>();
    k5_gather<<<T_ + 1, 256>>>(out);
}